// round 16
// baseline (speedup 1.0000x reference)
#include <cuda_runtime.h>
#include <cuda_fp16.h>
#include <math.h>
#include <stdint.h>

#define TKN   8192
#define HID   1024
#define NE    8
#define TOPK  2
#define INTR  2048
#define SINT  1024
#define SLOTS_PAD (TKN * TOPK + NE * 128)   // padded slot space (128-aligned per expert)
#define YT_EXP 136                           // expert slot tiles
#define YT_SH  64                            // shared-expert token tiles (8192/128)
#define YT_TOT (YT_EXP + YT_SH)

// ===================== scratch (device globals; no allocations) =====================
__device__ int   g_counts[NE];
__device__ int   g_offsets[NE];   // 128-aligned prefix
__device__ int   g_ptotal;        // padded total slots
__device__ int   g_cursor[NE];
__device__ __align__(16) int   g_tok[SLOTS_PAD];
__device__ __align__(16) float g_gate[SLOTS_PAD];
__device__ __align__(16) int   g_slot_of[TKN * TOPK];
__device__ __align__(16) int   g_topidx[TKN * TOPK];
__device__ __align__(16) float g_topgate[TKN * TOPK];

// fp16 operands (single precision-rounded copies)
__device__ __align__(16) __half g_x[(size_t)TKN * HID];
__device__ __align__(16) __half g_h[(size_t)SLOTS_PAD * INTR];
__device__ __align__(16) __half g_hs[(size_t)TKN * SINT];
__device__ __align__(16) __half g_wfc[(size_t)NE * INTR * HID];
__device__ __align__(16) __half g_wpj[(size_t)NE * HID * INTR];
__device__ __align__(16) __half g_wfcs[(size_t)SINT * HID];
__device__ __align__(16) __half g_wpjs[(size_t)HID * SINT];
__device__ __align__(16) float g_partial[(size_t)SLOTS_PAD * HID];

__device__ __forceinline__ float gelu_exact(float x) {
    return 0.5f * x * (1.0f + erff(x * 0.7071067811865476f));
}

// ===================== PTX helpers (base-target only) =====================
__device__ __forceinline__ uint32_t smem_to_u32(const void* p) {
    uint32_t a;
    asm("{ .reg .u64 t; cvta.to.shared.u64 t, %1; cvt.u32.u64 %0, t; }" : "=r"(a) : "l"(p));
    return a;
}
__device__ __forceinline__ void cp_async16(uint32_t dst, const void* src, uint32_t sz) {
    asm volatile(
        "{ .reg .u64 g; cvta.to.global.u64 g, %1;\n\t"
        "cp.async.cg.shared.global [%0], [g], 16, %2; }"
        :: "r"(dst), "l"(src), "r"(sz));
}
#define CP_COMMIT() asm volatile("cp.async.commit_group;" ::: "memory")
#define CP_WAIT(n)  asm volatile("cp.async.wait_group %0;" :: "n"(n) : "memory")

__device__ __forceinline__ void ldsm4(uint32_t& r0, uint32_t& r1, uint32_t& r2, uint32_t& r3,
                                      uint32_t addr) {
    asm volatile("ldmatrix.sync.aligned.m8n8.x4.shared.b16 {%0,%1,%2,%3}, [%4];"
        : "=r"(r0), "=r"(r1), "=r"(r2), "=r"(r3) : "r"(addr));
}
__device__ __forceinline__ void mma16816(float* c, const uint32_t* a, const uint32_t* b) {
    asm volatile(
        "mma.sync.aligned.m16n8k16.row.col.f32.f16.f16.f32 "
        "{%0,%1,%2,%3}, {%4,%5,%6,%7}, {%8,%9}, {%0,%1,%2,%3};"
        : "+f"(c[0]), "+f"(c[1]), "+f"(c[2]), "+f"(c[3])
        : "r"(a[0]), "r"(a[1]), "r"(a[2]), "r"(a[3]), "r"(b[0]), "r"(b[1]));
}

// swizzled smem layout: rows x 64B (4 chunks of 16B), conflict-free.
__device__ __forceinline__ uint32_t swz(int r, int c) {
    return (uint32_t)(r * 64 + ((c ^ ((r >> 1) & 3)) << 4));
}

// ===================== small kernels =====================
__global__ void init_kernel() {
    int i = threadIdx.x;
    if (i < NE) g_counts[i] = 0;
}

__global__ void router_kernel(const float* __restrict__ x, const float* __restrict__ wg) {
    __shared__ float s_wg[NE * HID];
    int tid = threadIdx.x;
    for (int i = tid; i < NE * HID; i += blockDim.x) s_wg[i] = wg[i];
    __syncthreads();
    int warp = tid >> 5, lane = tid & 31;
    int t = blockIdx.x * (blockDim.x >> 5) + warp;
    if (t >= TKN) return;
    float acc[NE];
#pragma unroll
    for (int e = 0; e < NE; e++) acc[e] = 0.0f;
    const float* xp = x + (size_t)t * HID;
    for (int k = lane; k < HID; k += 32) {
        float xv = xp[k];
#pragma unroll
        for (int e = 0; e < NE; e++) acc[e] = fmaf(xv, s_wg[e * HID + k], acc[e]);
    }
#pragma unroll
    for (int e = 0; e < NE; e++) {
#pragma unroll
        for (int o = 16; o > 0; o >>= 1) acc[e] += __shfl_xor_sync(0xffffffffu, acc[e], o);
    }
    if (lane == 0) {
        int i0 = 0; float v0 = acc[0];
#pragma unroll
        for (int e = 1; e < NE; e++) { if (acc[e] > v0) { v0 = acc[e]; i0 = e; } }
        int i1 = -1; float v1 = -1e30f;
#pragma unroll
        for (int e = 0; e < NE; e++) { if (e != i0 && acc[e] > v1) { v1 = acc[e]; i1 = e; } }
        float e1 = expf(v1 - v0);
        float denom = 1.0f + e1;
        g_topidx[t * 2 + 0] = i0;  g_topgate[t * 2 + 0] = 1.0f / denom;
        g_topidx[t * 2 + 1] = i1;  g_topgate[t * 2 + 1] = e1 / denom;
        atomicAdd(&g_counts[i0], 1);
        atomicAdd(&g_counts[i1], 1);
    }
}

// 128-aligned prefix
__global__ void prefix_kernel() {
    if (threadIdx.x == 0) {
        int s = 0;
        for (int e = 0; e < NE; e++) {
            g_offsets[e] = s;
            s += (g_counts[e] + 127) & ~127;
            g_cursor[e] = 0;
        }
        g_ptotal = s;
    }
}

__global__ void scatter_kernel() {
    int t = blockIdx.x * blockDim.x + threadIdx.x;
    if (t >= TKN) return;
#pragma unroll
    for (int k = 0; k < TOPK; k++) {
        int e = g_topidx[t * 2 + k];
        int slot = atomicAdd(&g_cursor[e], 1);
        int pos = g_offsets[e] + slot;
        g_tok[pos] = t;
        g_gate[pos] = g_topgate[t * 2 + k];
        g_slot_of[t * 2 + k] = pos;
    }
}

// fp32 -> fp16 (round-to-nearest)
__global__ void cvt_kernel(const float* __restrict__ src, __half* __restrict__ dst, int n) {
    int i = (blockIdx.x * blockDim.x + threadIdx.x) * 4;
    if (i >= n) return;
    float4 v = *reinterpret_cast<const float4*>(src + i);
    uint2 p;
    p.x = (uint32_t)__half_as_ushort(__float2half_rn(v.x)) |
          ((uint32_t)__half_as_ushort(__float2half_rn(v.y)) << 16);
    p.y = (uint32_t)__half_as_ushort(__float2half_rn(v.z)) |
          ((uint32_t)__half_as_ushort(__float2half_rn(v.w)) << 16);
    *reinterpret_cast<uint2*>(dst + i) = p;
}

// ===================== merged mma.sync grouped GEMM =====================
// Block tile 128x128, BK=32 fp16. 4 warps (2 x 2), warp tile 64x64.
// 5-stage cp.async pipeline; 2 CTAs/SM; hoisted loader addressing.
// PHASE 0 (FC):   y<YT_EXP expert fc tiles (N=2048); y>=YT_EXP shared fc (N=1024, bn<8)
// PHASE 1 (PROJ): y<YT_EXP expert proj (K=2048, gate->partial); y>=YT_EXP shared proj (K=1024 ->out)
#define TILE_B   8192
#define STAGE_B  16384
#define NSTAGE   5
#define SMEM_MMA (NSTAGE * STAGE_B)

template <int PHASE>
__global__ void __launch_bounds__(128, 2) mma_gemm(float* __restrict__ outp)
{
    const int bm = blockIdx.y;
    const int bn = blockIdx.x;
    const bool expSeg = (bm < YT_EXP);

    int rows = TKN, base = 0, e = 0;
    int kd, nd;
    if (expSeg) {
        const int slot0 = bm * 128;
        if (slot0 >= g_ptotal) return;
#pragma unroll
        for (int k = 1; k < NE; k++) if (g_offsets[k] <= slot0) e = k;
        rows = g_counts[e];
        base = g_offsets[e];
        kd = (PHASE == 0) ? HID : INTR;
        nd = (PHASE == 0) ? INTR : HID;
    } else {
        if (PHASE == 0 && bn >= SINT / 128) return;
        kd = HID;
        nd = (PHASE == 0) ? SINT : HID;
    }
    const int ITERS = kd / 32;
    const int trow0 = (bm - YT_EXP) * 128;   // token row base for shared segment

    extern __shared__ char smem[];
    const uint32_t sb = smem_to_u32(smem);

    const int tid = threadIdx.x;
    const int wid = tid >> 5, lid = tid & 31;
    const int warp_m = wid & 1;
    const int warp_n = wid >> 1;

    const __half *A, *B;
    if (PHASE == 0) {
        A = g_x;  // stride HID both segments
        B = expSeg ? (g_wfc + (size_t)e * INTR * HID) : g_wfcs;
    } else {
        A = expSeg ? g_h : g_hs;
        B = expSeg ? (g_wpj + (size_t)e * HID * INTR) : g_wpjs;
    }

    float acc[4][8][4];
#pragma unroll
    for (int i = 0; i < 4; i++)
#pragma unroll
        for (int j = 0; j < 8; j++)
#pragma unroll
            for (int q = 0; q < 4; q++) acc[i][j][q] = 0.0f;

    // ---- hoisted loader state: per thread 4 A-units + 4 B-units ----
    const int lch = tid & 3;
    const int lr0 = tid >> 2;
    const __half* srcA[4];
    const __half* srcB[4];
    uint32_t dA[4], dB[4], szA[4];
#pragma unroll
    for (int k = 0; k < 4; k++) {
        const int r = lr0 + 32 * k;
        dA[k] = swz(r, lch);
        dB[k] = TILE_B + swz(r, lch);
        size_t srow; szA[k] = 16;
        if (expSeg) {
            int slot = bm * 128 + r;
            if (PHASE == 0) {
                if (slot - base < rows) srow = (size_t)g_tok[slot];
                else { srow = 0; szA[k] = 0; }
            } else {
                if (slot - base < rows) srow = (size_t)slot;
                else { srow = (size_t)base; szA[k] = 0; }
            }
        } else {
            srow = (size_t)(trow0 + r);
        }
        srcA[k] = A + srow * kd + lch * 8;
        srcB[k] = B + (size_t)(bn * 128 + r) * kd + lch * 8;
    }

    auto load_stage = [&](int it) {
        const uint32_t stBase = sb + (uint32_t)(it % NSTAGE) * STAGE_B;
        const int koff = it * 32;
#pragma unroll
        for (int k = 0; k < 4; k++) {
            cp_async16(stBase + dA[k], srcA[k] + koff, szA[k]);
            cp_async16(stBase + dB[k], srcB[k] + koff, 16);
        }
    };

    auto compute_stage = [&](int s) {
        const uint32_t aB = sb + (uint32_t)s * STAGE_B;
        const uint32_t bB = aB + TILE_B;
#pragma unroll
        for (int h = 0; h < 2; h++) {
            uint32_t a[4][4], b[8][2];
            const int a_ch = h * 2 + (lid >> 4);
            const int b_ch = h * 2 + ((lid >> 3) & 1);
            const int arow0 = warp_m * 64 + (lid & 7) + ((lid >> 3) & 1) * 8;
#pragma unroll
            for (int jj = 0; jj < 4; jj++) {
                int nrow = warp_n * 64 + jj * 16 + ((lid >> 4) & 1) * 8 + (lid & 7);
                uint32_t bd = bB + swz(nrow, b_ch);
                uint32_t r0, r1, r2, r3;
                ldsm4(r0, r1, r2, r3, bd);
                b[2 * jj][0] = r0; b[2 * jj][1] = r1;
                b[2 * jj + 1][0] = r2; b[2 * jj + 1][1] = r3;
            }
#pragma unroll
            for (int i = 0; i < 4; i++) {
                uint32_t ad = aB + swz(arow0 + i * 16, a_ch);
                ldsm4(a[i][0], a[i][1], a[i][2], a[i][3], ad);
            }
#pragma unroll
            for (int i = 0; i < 4; i++)
#pragma unroll
                for (int j = 0; j < 8; j++) mma16816(acc[i][j], a[i], b[j]);
        }
    };

    // -------- 5-stage pipeline, single sync per iteration --------
    load_stage(0); CP_COMMIT();
    load_stage(1); CP_COMMIT();
    load_stage(2); CP_COMMIT();
    load_stage(3); CP_COMMIT();
#pragma unroll 1
    for (int it = 0; it < ITERS; ++it) {
        CP_WAIT(3);
        __syncthreads();
        if (it + 4 < ITERS) load_stage(it + 4);
        CP_COMMIT();
        compute_stage(it % NSTAGE);
    }

    // -------- epilogue --------
    const int g = lid >> 2, t4 = lid & 3;
#pragma unroll
    for (int i = 0; i < 4; i++) {
#pragma unroll
        for (int half = 0; half < 2; half++) {
            const int r = warp_m * 64 + i * 16 + g + half * 8;
            int srow;                  // destination row index
            if (expSeg) {
                srow = bm * 128 + r;   // slot id
                if (srow - base >= rows) continue;
            } else {
                srow = trow0 + r;      // token row
            }
            float gate = 1.0f;
            if (PHASE == 1 && expSeg) gate = g_gate[srow];
#pragma unroll
            for (int j = 0; j < 8; j++) {
                float c0 = acc[i][j][half * 2 + 0];
                float c1 = acc[i][j][half * 2 + 1];
                int col = bn * 128 + warp_n * 64 + j * 8 + t4 * 2;
                if (PHASE == 0) {
                    float f0 = gelu_exact(c0), f1 = gelu_exact(c1);
                    uint32_t hp = (uint32_t)__half_as_ushort(__float2half_rn(f0)) |
                                  ((uint32_t)__half_as_ushort(__float2half_rn(f1)) << 16);
                    __half* H = expSeg ? g_h : g_hs;
                    size_t off = (size_t)srow * nd + col;
                    *reinterpret_cast<uint32_t*>(H + off) = hp;
                } else if (expSeg) {
                    size_t off = (size_t)srow * HID + col;
                    float2 v = make_float2(gate * c0, gate * c1);
                    *reinterpret_cast<float2*>(g_partial + off) = v;
                } else {
                    size_t off = (size_t)srow * HID + col;
                    float2 v = make_float2(c0, c1);
                    *reinterpret_cast<float2*>(outp + off) = v;
                }
            }
        }
    }
}

// ---------------- combine (coalesced): out += partial[slot0] + partial[slot1] ----------------
__global__ void combine_kernel(float* __restrict__ out) {
    constexpr int NV = HID / 4;
    int idx = blockIdx.x * blockDim.x + threadIdx.x;
    if (idx >= TKN * NV) return;
    int t = idx / NV, n4 = idx % NV;
    int s0 = g_slot_of[t * 2 + 0];
    int s1 = g_slot_of[t * 2 + 1];
    float4 o = reinterpret_cast<float4*>(out)[idx];
    const float4* P = reinterpret_cast<const float4*>(g_partial);
    float4 p0 = P[(size_t)s0 * NV + n4];
    float4 p1 = P[(size_t)s1 * NV + n4];
    o.x += p0.x + p1.x;
    o.y += p0.y + p1.y;
    o.z += p0.z + p1.z;
    o.w += p0.w + p1.w;
    reinterpret_cast<float4*>(out)[idx] = o;
}

// ===================== launch (stream-forked DAG, capture-safe) =====================
extern "C" void kernel_launch(void* const* d_in, const int* in_sizes, int n_in,
                              void* d_out, int out_size) {
    (void)in_sizes; (void)n_in; (void)out_size;
    const float* x      = (const float*)d_in[0];
    const float* wg     = (const float*)d_in[1];
    const float* wfc    = (const float*)d_in[2];
    const float* wproj  = (const float*)d_in[3];
    const float* wfcs   = (const float*)d_in[4];
    const float* wprojs = (const float*)d_in[5];
    float* out = (float*)d_out;

    static cudaStream_t s1, s2;
    static cudaEvent_t evStart, evFCin, evPJin;
    static bool inited = false;
    if (!inited) {
        cudaFuncSetAttribute(mma_gemm<0>, cudaFuncAttributeMaxDynamicSharedMemorySize, SMEM_MMA);
        cudaFuncSetAttribute(mma_gemm<1>, cudaFuncAttributeMaxDynamicSharedMemorySize, SMEM_MMA);
        cudaStreamCreateWithFlags(&s1, cudaStreamNonBlocking);
        cudaStreamCreateWithFlags(&s2, cudaStreamNonBlocking);
        cudaEventCreateWithFlags(&evStart, cudaEventDisableTiming);
        cudaEventCreateWithFlags(&evFCin,  cudaEventDisableTiming);
        cudaEventCreateWithFlags(&evPJin,  cudaEventDisableTiming);
        inited = true;
    }

    __half *hx, *hwfc, *hwpj, *hwfcs, *hwpjs;
    cudaGetSymbolAddress((void**)&hx,    g_x);
    cudaGetSymbolAddress((void**)&hwfc,  g_wfc);
    cudaGetSymbolAddress((void**)&hwpj,  g_wpj);
    cudaGetSymbolAddress((void**)&hwfcs, g_wfcs);
    cudaGetSymbolAddress((void**)&hwpjs, g_wpjs);

    // fork point on the capture (default) stream
    init_kernel<<<1, 32, 0, 0>>>();
    cudaEventRecord(evStart, 0);
    cudaStreamWaitEvent(s1, evStart, 0);
    cudaStreamWaitEvent(s2, evStart, 0);

    // --- s1: FC-side conversions (x, wfcs, wfc) ---
    cvt_kernel<<<(TKN * HID) / 1024, 256, 0, s1>>>(x, hx, TKN * HID);
    cvt_kernel<<<(SINT * HID) / 1024, 256, 0, s1>>>(wfcs, hwfcs, SINT * HID);
    cvt_kernel<<<(NE * INTR * HID) / 1024, 256, 0, s1>>>(wfc, hwfc, NE * INTR * HID);
    cudaEventRecord(evFCin, s1);

    // --- s2: PROJ-side conversions (wpj, wpjs) ---
    cvt_kernel<<<(NE * HID * INTR) / 1024, 256, 0, s2>>>(wproj, hwpj, NE * HID * INTR);
    cvt_kernel<<<(HID * SINT) / 1024, 256, 0, s2>>>(wprojs, hwpjs, HID * SINT);
    cudaEventRecord(evPJin, s2);

    // --- stream 0: routing chain, merged GEMMs, combine ---
    router_kernel<<<TKN / 8, 256, 0, 0>>>(x, wg);
    prefix_kernel<<<1, 32, 0, 0>>>();
    scatter_kernel<<<TKN / 256, 256, 0, 0>>>();

    cudaStreamWaitEvent(0, evFCin, 0);
    mma_gemm<0><<<dim3(INTR / 128, YT_TOT, 1), 128, SMEM_MMA, 0>>>(nullptr);
    cudaStreamWaitEvent(0, evPJin, 0);
    mma_gemm<1><<<dim3(HID / 128, YT_TOT, 1), 128, SMEM_MMA, 0>>>(out);

    combine_kernel<<<(TKN * (HID / 4)) / 256, 256, 0, 0>>>(out);
}

// round 17
// speedup vs baseline: 1.0331x; 1.0331x over previous
#include <cuda_runtime.h>
#include <cuda_fp16.h>
#include <math.h>
#include <stdint.h>

#define TKN   8192
#define HID   1024
#define NE    8
#define TOPK  2
#define INTR  2048
#define SINT  1024
#define SLOTS_PAD (TKN * TOPK + NE * 128)   // padded slot space (128-aligned per expert)
#define YTILES 136                           // SLOTS_PAD / 128

// ===================== scratch (device globals; no allocations) =====================
__device__ int   g_counts[NE];    // zeroed at end of combine (and statically for run 1)
__device__ int   g_offsets[NE];   // 128-aligned prefix
__device__ int   g_ptotal;        // padded total slots
__device__ int   g_cursor[NE];
__device__ int   g_done;          // router last-CTA counter (self-resetting)
__device__ __align__(16) int   g_tok[SLOTS_PAD];
__device__ __align__(16) float g_gate[SLOTS_PAD];
__device__ __align__(16) int   g_slot_of[TKN * TOPK];
__device__ __align__(16) int   g_topidx[TKN * TOPK];
__device__ __align__(16) float g_topgate[TKN * TOPK];

// fp16 operands (single precision-rounded copies)
__device__ __align__(16) __half g_x[(size_t)TKN * HID];
__device__ __align__(16) __half g_h[(size_t)SLOTS_PAD * INTR];
__device__ __align__(16) __half g_hs[(size_t)TKN * SINT];
__device__ __align__(16) __half g_wfc[(size_t)NE * INTR * HID];
__device__ __align__(16) __half g_wpj[(size_t)NE * HID * INTR];
__device__ __align__(16) __half g_wfcs[(size_t)SINT * HID];
__device__ __align__(16) __half g_wpjs[(size_t)HID * SINT];
__device__ __align__(16) float g_partial[(size_t)SLOTS_PAD * HID];

__device__ __forceinline__ float gelu_exact(float x) {
    return 0.5f * x * (1.0f + erff(x * 0.7071067811865476f));
}

// ===================== PTX helpers (base-target only) =====================
__device__ __forceinline__ uint32_t smem_to_u32(const void* p) {
    uint32_t a;
    asm("{ .reg .u64 t; cvta.to.shared.u64 t, %1; cvt.u32.u64 %0, t; }" : "=r"(a) : "l"(p));
    return a;
}
__device__ __forceinline__ void cp_async16(uint32_t dst, const void* src, uint32_t sz) {
    asm volatile(
        "{ .reg .u64 g; cvta.to.global.u64 g, %1;\n\t"
        "cp.async.cg.shared.global [%0], [g], 16, %2; }"
        :: "r"(dst), "l"(src), "r"(sz));
}
#define CP_COMMIT() asm volatile("cp.async.commit_group;" ::: "memory")
#define CP_WAIT(n)  asm volatile("cp.async.wait_group %0;" :: "n"(n) : "memory")

__device__ __forceinline__ void ldsm4(uint32_t& r0, uint32_t& r1, uint32_t& r2, uint32_t& r3,
                                      uint32_t addr) {
    asm volatile("ldmatrix.sync.aligned.m8n8.x4.shared.b16 {%0,%1,%2,%3}, [%4];"
        : "=r"(r0), "=r"(r1), "=r"(r2), "=r"(r3) : "r"(addr));
}
__device__ __forceinline__ void mma16816(float* c, const uint32_t* a, const uint32_t* b) {
    asm volatile(
        "mma.sync.aligned.m16n8k16.row.col.f32.f16.f16.f32 "
        "{%0,%1,%2,%3}, {%4,%5,%6,%7}, {%8,%9}, {%0,%1,%2,%3};"
        : "+f"(c[0]), "+f"(c[1]), "+f"(c[2]), "+f"(c[3])
        : "r"(a[0]), "r"(a[1]), "r"(a[2]), "r"(a[3]), "r"(b[0]), "r"(b[1]));
}

// swizzled smem layout: rows x 64B (4 chunks of 16B), conflict-free.
__device__ __forceinline__ uint32_t swz(int r, int c) {
    return (uint32_t)(r * 64 + ((c ^ ((r >> 1) & 3)) << 4));
}

// ===================== small kernels =====================
// router + inline last-CTA prefix (replaces init/prefix launches)
__global__ void router_kernel(const float* __restrict__ x, const float* __restrict__ wg) {
    __shared__ float s_wg[NE * HID];
    int tid = threadIdx.x;
    for (int i = tid; i < NE * HID; i += blockDim.x) s_wg[i] = wg[i];
    __syncthreads();
    int warp = tid >> 5, lane = tid & 31;
    int t = blockIdx.x * (blockDim.x >> 5) + warp;
    if (t < TKN) {
        float acc[NE];
#pragma unroll
        for (int e = 0; e < NE; e++) acc[e] = 0.0f;
        const float* xp = x + (size_t)t * HID;
        for (int k = lane; k < HID; k += 32) {
            float xv = xp[k];
#pragma unroll
            for (int e = 0; e < NE; e++) acc[e] = fmaf(xv, s_wg[e * HID + k], acc[e]);
        }
#pragma unroll
        for (int e = 0; e < NE; e++) {
#pragma unroll
            for (int o = 16; o > 0; o >>= 1) acc[e] += __shfl_xor_sync(0xffffffffu, acc[e], o);
        }
        if (lane == 0) {
            int i0 = 0; float v0 = acc[0];
#pragma unroll
            for (int e = 1; e < NE; e++) { if (acc[e] > v0) { v0 = acc[e]; i0 = e; } }
            int i1 = -1; float v1 = -1e30f;
#pragma unroll
            for (int e = 0; e < NE; e++) { if (e != i0 && acc[e] > v1) { v1 = acc[e]; i1 = e; } }
            float e1 = expf(v1 - v0);
            float denom = 1.0f + e1;
            g_topidx[t * 2 + 0] = i0;  g_topgate[t * 2 + 0] = 1.0f / denom;
            g_topidx[t * 2 + 1] = i1;  g_topgate[t * 2 + 1] = e1 / denom;
            atomicAdd(&g_counts[i0], 1);
            atomicAdd(&g_counts[i1], 1);
        }
    }
    // last-CTA inline 128-aligned prefix
    __syncthreads();
    if (tid == 0) {
        __threadfence();
        int old = atomicAdd(&g_done, 1);
        if (old == (int)gridDim.x - 1) {
            int s = 0;
#pragma unroll
            for (int e = 0; e < NE; e++) {
                g_offsets[e] = s;
                s += (g_counts[e] + 127) & ~127;
                g_cursor[e] = 0;
            }
            g_ptotal = s;
            g_done = 0;
            __threadfence();
        }
    }
}

__global__ void scatter_kernel() {
    int t = blockIdx.x * blockDim.x + threadIdx.x;
    if (t >= TKN) return;
#pragma unroll
    for (int k = 0; k < TOPK; k++) {
        int e = g_topidx[t * 2 + k];
        int slot = atomicAdd(&g_cursor[e], 1);
        int pos = g_offsets[e] + slot;
        g_tok[pos] = t;
        g_gate[pos] = g_topgate[t * 2 + k];
        g_slot_of[t * 2 + k] = pos;
    }
}

// fp32 -> fp16 (round-to-nearest)
__global__ void cvt_kernel(const float* __restrict__ src, __half* __restrict__ dst, int n) {
    int i = (blockIdx.x * blockDim.x + threadIdx.x) * 4;
    if (i >= n) return;
    float4 v = *reinterpret_cast<const float4*>(src + i);
    uint2 p;
    p.x = (uint32_t)__half_as_ushort(__float2half_rn(v.x)) |
          ((uint32_t)__half_as_ushort(__float2half_rn(v.y)) << 16);
    p.y = (uint32_t)__half_as_ushort(__float2half_rn(v.z)) |
          ((uint32_t)__half_as_ushort(__float2half_rn(v.w)) << 16);
    *reinterpret_cast<uint2*>(dst + i) = p;
}

// ===================== mma.sync grouped GEMM (R14-proven) =====================
#define TILE_B   8192
#define STAGE_B  16384
#define NSTAGE   5
#define SMEM_MMA (NSTAGE * STAGE_B)

template <int MODE>
__global__ void __launch_bounds__(128, 2) mma_gemm(float* __restrict__ outp)
{
    constexpr int KD = (MODE == 1) ? INTR : HID;
    constexpr int ND = (MODE == 0) ? INTR : ((MODE == 2) ? SINT : HID);
    constexpr int ITERS = KD / 32;

    int rows, base, e = 0;
    const int bm = blockIdx.y;
    if (MODE <= 1) {
        const int slot0 = bm * 128;
        if (slot0 >= g_ptotal) return;
#pragma unroll
        for (int k = 1; k < NE; k++) if (g_offsets[k] <= slot0) e = k;
        rows = g_counts[e];
        base = g_offsets[e];
    } else {
        rows = TKN; base = 0;
        if (bm * 128 >= rows) return;
    }
    const int bn = blockIdx.x;

    extern __shared__ char smem[];
    const uint32_t sb = smem_to_u32(smem);

    const int tid = threadIdx.x;
    const int wid = tid >> 5, lid = tid & 31;
    const int warp_m = wid & 1;
    const int warp_n = wid >> 1;

    const __half *A, *B;
    if (MODE == 0)      A = g_x;
    else if (MODE == 1) A = g_h;
    else if (MODE == 2) A = g_x;
    else                A = g_hs;
    if (MODE == 0)      B = g_wfc  + (size_t)e * INTR * HID;
    else if (MODE == 1) B = g_wpj  + (size_t)e * HID * INTR;
    else if (MODE == 2) B = g_wfcs;
    else                B = g_wpjs;

    float acc[4][8][4];
#pragma unroll
    for (int i = 0; i < 4; i++)
#pragma unroll
        for (int j = 0; j < 8; j++)
#pragma unroll
            for (int q = 0; q < 4; q++) acc[i][j][q] = 0.0f;

    auto load_stage = [&](int it) {
        const int s = it % NSTAGE;
        const int k0 = it * 32;
        const uint32_t stBase = sb + (uint32_t)s * STAGE_B;
#pragma unroll
        for (int l = 0; l < 8; l++) {
            int u = tid + l * 128;
            if (u < 512) {
                int r = u >> 2, ch = u & 3;
                uint32_t szA = 16;
                size_t srow;
                if (MODE == 0) {
                    int slot = bm * 128 + r;
                    if (slot - base < rows) srow = (size_t)g_tok[slot];
                    else { srow = 0; szA = 0; }
                } else if (MODE == 1) {
                    int slot = bm * 128 + r;
                    if (slot - base < rows) srow = (size_t)slot;
                    else { srow = (size_t)base; szA = 0; }
                } else srow = (size_t)(bm * 128 + r);
                cp_async16(stBase + swz(r, ch), A + srow * KD + k0 + ch * 8, szA);
            } else {
                int v = u - 512;
                int r = v >> 2, ch = v & 3;
                size_t boff = (size_t)(bn * 128 + r) * KD + k0 + ch * 8;
                cp_async16(stBase + TILE_B + swz(r, ch), B + boff, 16);
            }
        }
    };

    auto compute_stage = [&](int s) {
        const uint32_t aB = sb + (uint32_t)s * STAGE_B;
        const uint32_t bB = aB + TILE_B;
#pragma unroll
        for (int h = 0; h < 2; h++) {
            uint32_t a[4][4], b[8][2];
            const int a_ch = h * 2 + (lid >> 4);
            const int b_ch = h * 2 + ((lid >> 3) & 1);
            const int arow0 = warp_m * 64 + (lid & 7) + ((lid >> 3) & 1) * 8;
#pragma unroll
            for (int jj = 0; jj < 4; jj++) {
                int nrow = warp_n * 64 + jj * 16 + ((lid >> 4) & 1) * 8 + (lid & 7);
                uint32_t bd = bB + swz(nrow, b_ch);
                uint32_t r0, r1, r2, r3;
                ldsm4(r0, r1, r2, r3, bd);
                b[2 * jj][0] = r0; b[2 * jj][1] = r1;
                b[2 * jj + 1][0] = r2; b[2 * jj + 1][1] = r3;
            }
#pragma unroll
            for (int i = 0; i < 4; i++) {
                uint32_t ad = aB + swz(arow0 + i * 16, a_ch);
                ldsm4(a[i][0], a[i][1], a[i][2], a[i][3], ad);
            }
#pragma unroll
            for (int i = 0; i < 4; i++)
#pragma unroll
                for (int j = 0; j < 8; j++) mma16816(acc[i][j], a[i], b[j]);
        }
    };

    load_stage(0); CP_COMMIT();
    load_stage(1); CP_COMMIT();
    load_stage(2); CP_COMMIT();
    load_stage(3); CP_COMMIT();
#pragma unroll 1
    for (int it = 0; it < ITERS; ++it) {
        CP_WAIT(3);
        __syncthreads();
        if (it + 4 < ITERS) load_stage(it + 4);
        CP_COMMIT();
        compute_stage(it % NSTAGE);
    }

    const int g = lid >> 2, t4 = lid & 3;
#pragma unroll
    for (int i = 0; i < 4; i++) {
#pragma unroll
        for (int half = 0; half < 2; half++) {
            int srow = bm * 128 + warp_m * 64 + i * 16 + g + half * 8;
            if (MODE <= 1) { if (srow - base >= rows) continue; }
            else           { if (srow >= rows) continue; }
            float gate = 1.0f;
            if (MODE == 1) gate = g_gate[srow];
#pragma unroll
            for (int j = 0; j < 8; j++) {
                float c0 = acc[i][j][half * 2 + 0];
                float c1 = acc[i][j][half * 2 + 1];
                int col = bn * 128 + warp_n * 64 + j * 8 + t4 * 2;
                if (MODE == 0 || MODE == 2) {
                    float f0 = gelu_exact(c0), f1 = gelu_exact(c1);
                    uint32_t hp = (uint32_t)__half_as_ushort(__float2half_rn(f0)) |
                                  ((uint32_t)__half_as_ushort(__float2half_rn(f1)) << 16);
                    __half* H = (MODE == 0) ? g_h : g_hs;
                    size_t off = (size_t)srow * ND + col;
                    *reinterpret_cast<uint32_t*>(H + off) = hp;
                } else if (MODE == 1) {
                    size_t off = (size_t)srow * HID + col;
                    float2 v = make_float2(gate * c0, gate * c1);
                    *reinterpret_cast<float2*>(g_partial + off) = v;
                } else {
                    size_t off = (size_t)srow * HID + col;
                    float2 v = make_float2(c0, c1);
                    *reinterpret_cast<float2*>(outp + off) = v;
                }
            }
        }
    }
}

// ---------------- combine + state reset for next replay ----------------
__global__ void combine_kernel(float* __restrict__ out) {
    constexpr int NV = HID / 4;
    int idx = blockIdx.x * blockDim.x + threadIdx.x;
    if (blockIdx.x == 0 && threadIdx.x < NE) g_counts[threadIdx.x] = 0;  // reset for next run
    if (idx >= TKN * NV) return;
    int t = idx / NV, n4 = idx % NV;
    int s0 = g_slot_of[t * 2 + 0];
    int s1 = g_slot_of[t * 2 + 1];
    float4 o = reinterpret_cast<float4*>(out)[idx];
    const float4* P = reinterpret_cast<const float4*>(g_partial);
    float4 p0 = P[(size_t)s0 * NV + n4];
    float4 p1 = P[(size_t)s1 * NV + n4];
    o.x += p0.x + p1.x;
    o.y += p0.y + p1.y;
    o.z += p0.z + p1.z;
    o.w += p0.w + p1.w;
    reinterpret_cast<float4*>(out)[idx] = o;
}

// ===================== launch (stream-forked DAG, capture-safe) =====================
extern "C" void kernel_launch(void* const* d_in, const int* in_sizes, int n_in,
                              void* d_out, int out_size) {
    (void)in_sizes; (void)n_in; (void)out_size;
    const float* x      = (const float*)d_in[0];
    const float* wg     = (const float*)d_in[1];
    const float* wfc    = (const float*)d_in[2];
    const float* wproj  = (const float*)d_in[3];
    const float* wfcs   = (const float*)d_in[4];
    const float* wprojs = (const float*)d_in[5];
    float* out = (float*)d_out;

    static cudaStream_t s1, s2;
    static cudaEvent_t evStart, evX, evWfc, evWpj, evWpjs, evM3;
    static bool inited = false;
    if (!inited) {
        cudaFuncSetAttribute(mma_gemm<0>, cudaFuncAttributeMaxDynamicSharedMemorySize, SMEM_MMA);
        cudaFuncSetAttribute(mma_gemm<1>, cudaFuncAttributeMaxDynamicSharedMemorySize, SMEM_MMA);
        cudaFuncSetAttribute(mma_gemm<2>, cudaFuncAttributeMaxDynamicSharedMemorySize, SMEM_MMA);
        cudaFuncSetAttribute(mma_gemm<3>, cudaFuncAttributeMaxDynamicSharedMemorySize, SMEM_MMA);
        cudaStreamCreateWithFlags(&s1, cudaStreamNonBlocking);
        cudaStreamCreateWithFlags(&s2, cudaStreamNonBlocking);
        cudaEventCreateWithFlags(&evStart, cudaEventDisableTiming);
        cudaEventCreateWithFlags(&evX,     cudaEventDisableTiming);
        cudaEventCreateWithFlags(&evWfc,   cudaEventDisableTiming);
        cudaEventCreateWithFlags(&evWpj,   cudaEventDisableTiming);
        cudaEventCreateWithFlags(&evWpjs,  cudaEventDisableTiming);
        cudaEventCreateWithFlags(&evM3,    cudaEventDisableTiming);
        inited = true;
    }

    __half *hx, *hwfc, *hwpj, *hwfcs, *hwpjs;
    cudaGetSymbolAddress((void**)&hx,    g_x);
    cudaGetSymbolAddress((void**)&hwfc,  g_wfc);
    cudaGetSymbolAddress((void**)&hwpj,  g_wpj);
    cudaGetSymbolAddress((void**)&hwfcs, g_wfcs);
    cudaGetSymbolAddress((void**)&hwpjs, g_wpjs);

    // fork point on the capture (default) stream
    cudaEventRecord(evStart, 0);
    cudaStreamWaitEvent(s1, evStart, 0);
    cudaStreamWaitEvent(s2, evStart, 0);

    // --- s1: activation cvt + shared-expert path ---
    cvt_kernel<<<(TKN * HID) / 1024, 256, 0, s1>>>(x, hx, TKN * HID);
    cudaEventRecord(evX, s1);
    cvt_kernel<<<(SINT * HID) / 1024, 256, 0, s1>>>(wfcs, hwfcs, SINT * HID);
    mma_gemm<2><<<dim3(SINT / 128, TKN / 128, 1), 128, SMEM_MMA, s1>>>(nullptr);

    // --- s2: weight conversions ---
    cvt_kernel<<<(NE * INTR * HID) / 1024, 256, 0, s2>>>(wfc, hwfc, NE * INTR * HID);
    cudaEventRecord(evWfc, s2);
    cvt_kernel<<<(NE * HID * INTR) / 1024, 256, 0, s2>>>(wproj, hwpj, NE * HID * INTR);
    cudaEventRecord(evWpj, s2);
    cvt_kernel<<<(HID * SINT) / 1024, 256, 0, s2>>>(wprojs, hwpjs, HID * SINT);
    cudaEventRecord(evWpjs, s2);

    // --- s1 continues: shared proj (needs wpjs + g_hs) ---
    cudaStreamWaitEvent(s1, evWpjs, 0);
    mma_gemm<3><<<dim3(HID / 128, TKN / 128, 1), 128, SMEM_MMA, s1>>>(out);
    cudaEventRecord(evM3, s1);

    // --- stream 0: routing chain (router includes inline prefix), expert GEMMs, combine ---
    router_kernel<<<TKN / 8, 256, 0, 0>>>(x, wg);
    scatter_kernel<<<TKN / 256, 256, 0, 0>>>();

    cudaStreamWaitEvent(0, evX, 0);
    cudaStreamWaitEvent(0, evWfc, 0);
    mma_gemm<0><<<dim3(INTR / 128, YTILES, 1), 128, SMEM_MMA, 0>>>(nullptr);
    cudaStreamWaitEvent(0, evWpj, 0);
    mma_gemm<1><<<dim3(HID / 128, YTILES, 1), 128, SMEM_MMA, 0>>>(nullptr);

    cudaStreamWaitEvent(0, evM3, 0);
    combine_kernel<<<(TKN * (HID / 4)) / 256, 256, 0, 0>>>(out);
}